// round 1
// baseline (speedup 1.0000x reference)
#include <cuda_runtime.h>

// Problem constants
#define BATCH 512
#define FEAT  512
#define NID   64
#define GRP   8

// Scratch (no allocation allowed in kernel_launch)
__device__ float g_S[BATCH * BATCH];     // S = f_s @ f_t^T
__device__ float g_partial[NID];         // per-group partial sums

// ---------------------------------------------------------------------------
// Kernel 1: S = f_s @ f_t^T   (both [512,512] row-major, K contiguous)
// BM=64, BN=32, BK=32, 256 threads, 4x2 micro-tile, register prefetch.
// Grid: (512/32, 512/64) = (16, 8) = 128 blocks.
// ---------------------------------------------------------------------------
__global__ void __launch_bounds__(256) gemm_kernel(const float* __restrict__ fs,
                                                   const float* __restrict__ ft) {
    __shared__ float As[64][36];   // [m][k], pad 4 keeps float4 stores aligned
    __shared__ float Bs[32][34];   // [k][n], pad 2 keeps float2 reads conflict-free

    const int tid   = threadIdx.x;
    const int mTile = blockIdx.y * 64;
    const int nTile = blockIdx.x * 32;
    const int tm    = tid >> 4;          // 0..15 -> 4 rows each
    const int tn    = tid & 15;          // 0..15 -> 2 cols each

    const int lrow = tid >> 3;           // 0..31
    const int lkk  = (tid & 7) << 2;     // 0,4,...,28

    const float* aptr0 = fs + (mTile + lrow) * FEAT + lkk;
    const float* aptr1 = aptr0 + 32 * FEAT;
    const float* bptr  = ft + (nTile + lrow) * FEAT + lkk;

    // prologue prefetch
    float4 ra0 = *(const float4*)(aptr0);
    float4 ra1 = *(const float4*)(aptr1);
    float4 rb  = *(const float4*)(bptr);

    float acc[4][2] = {};

    for (int k0 = 0; k0 < FEAT; k0 += 32) {
        // commit prefetched tile to smem
        *(float4*)&As[lrow][lkk]      = ra0;
        *(float4*)&As[lrow + 32][lkk] = ra1;
        Bs[lkk + 0][lrow] = rb.x;
        Bs[lkk + 1][lrow] = rb.y;
        Bs[lkk + 2][lrow] = rb.z;
        Bs[lkk + 3][lrow] = rb.w;
        __syncthreads();

        // prefetch next k-slab while computing this one
        if (k0 + 32 < FEAT) {
            ra0 = *(const float4*)(aptr0 + k0 + 32);
            ra1 = *(const float4*)(aptr1 + k0 + 32);
            rb  = *(const float4*)(bptr  + k0 + 32);
        }

        #pragma unroll
        for (int k = 0; k < 32; k++) {
            float a0 = As[tm * 4 + 0][k];
            float a1 = As[tm * 4 + 1][k];
            float a2 = As[tm * 4 + 2][k];
            float a3 = As[tm * 4 + 3][k];
            float b0 = Bs[k][tn * 2 + 0];
            float b1 = Bs[k][tn * 2 + 1];
            acc[0][0] += a0 * b0;  acc[0][1] += a0 * b1;
            acc[1][0] += a1 * b0;  acc[1][1] += a1 * b1;
            acc[2][0] += a2 * b0;  acc[2][1] += a2 * b1;
            acc[3][0] += a3 * b0;  acc[3][1] += a3 * b1;
        }
        __syncthreads();
    }

    #pragma unroll
    for (int i = 0; i < 4; i++) {
        float2 v = make_float2(acc[i][0], acc[i][1]);
        *(float2*)&g_S[(mTile + tm * 4 + i) * BATCH + nTile + tn * 2] = v;
    }
}

// ---------------------------------------------------------------------------
// Kernel 2: per identity group n (64 blocks, 256 threads):
//   rk[b,i]     = 1 + sum_j relu(S[b,j] - S[b,i])       for b,i in group n
//   pos_rk[i,j] = 1 + sum_k relu(P[i,k] - P[i,j]),  P = diag 8x8 block of S
//   partial[n]  = sum_{i,j} pos_rk[i,j] / rk[n*8+i, n*8+j]
// ---------------------------------------------------------------------------
__global__ void __launch_bounds__(256) group_kernel() {
    __shared__ float Sr[GRP * BATCH];   // 8 rows x 512 cols = 16 KB
    __shared__ float rk_sm[64];
    __shared__ float wsum[2];

    const int n   = blockIdx.x;
    const int tid = threadIdx.x;

    // Load the group's 8 rows of S (4096 floats) with float4
    {
        const float4* src = (const float4*)(g_S + n * GRP * BATCH);
        float4* dst = (float4*)Sr;
        #pragma unroll
        for (int v = 0; v < 4; v++) dst[tid + v * 256] = src[tid + v * 256];
    }
    __syncthreads();

    // rk for 64 (row r, col-in-group i) pairs; 4 threads per pair.
    const int p = tid >> 2;   // pair 0..63
    const int q = tid & 3;    // quarter
    const int r = p >> 3;     // local row 0..7
    const int i = p & 7;      // col within group
    const float sbi = Sr[r * BATCH + n * GRP + i];
    const float* row = Sr + r * BATCH;

    float s = 0.f;
    #pragma unroll 8
    for (int jj = 0; jj < BATCH; jj += 16) {
        float4 v = *(const float4*)(row + jj + q * 4);
        s += fmaxf(v.x - sbi, 0.f) + fmaxf(v.y - sbi, 0.f)
           + fmaxf(v.z - sbi, 0.f) + fmaxf(v.w - sbi, 0.f);
    }
    s += __shfl_down_sync(0xffffffffu, s, 1);
    s += __shfl_down_sync(0xffffffffu, s, 2);
    if (q == 0) rk_sm[p] = 1.f + s;
    __syncthreads();

    // pos_rk + ratio: one thread per (i,j) pair (first 64 threads)
    float ratio = 0.f;
    if (tid < 64) {
        const int i2 = tid >> 3;
        const int j2 = tid & 7;
        const float* prow = Sr + i2 * BATCH + n * GRP;
        const float pij = prow[j2];
        float ps = 0.f;
        #pragma unroll
        for (int k = 0; k < GRP; k++) ps += fmaxf(prow[k] - pij, 0.f);
        ratio = (1.f + ps) / rk_sm[tid];
    }

    // deterministic reduce of ratio over warps 0 and 1
    #pragma unroll
    for (int o = 16; o > 0; o >>= 1)
        ratio += __shfl_down_sync(0xffffffffu, ratio, o);
    if (tid < 64 && (tid & 31) == 0) wsum[tid >> 5] = ratio;
    __syncthreads();
    if (tid == 0) g_partial[n] = wsum[0] + wsum[1];
}

// ---------------------------------------------------------------------------
// Kernel 3: final deterministic reduction -> out[0] = 1 - sum/ (g*B)
// ---------------------------------------------------------------------------
__global__ void final_kernel(float* __restrict__ out) {
    const int tid = threadIdx.x;  // 32 threads
    float v = g_partial[tid] + g_partial[tid + 32];
    #pragma unroll
    for (int o = 16; o > 0; o >>= 1)
        v += __shfl_down_sync(0xffffffffu, v, o);
    if (tid == 0) out[0] = 1.f - v * (1.f / 4096.f);  // g*B = 8*512
}

extern "C" void kernel_launch(void* const* d_in, const int* in_sizes, int n_in,
                              void* d_out, int out_size) {
    const float* fs = (const float*)d_in[0];
    const float* ft = (const float*)d_in[1];
    float* out = (float*)d_out;

    gemm_kernel<<<dim3(16, 8), 256>>>(fs, ft);
    group_kernel<<<NID, 256>>>();
    final_kernel<<<1, 32>>>(out);
}

// round 2
// speedup vs baseline: 1.2557x; 1.2557x over previous
#include <cuda_runtime.h>
#include <cuda_bf16.h>
#include <cstdint>

#define BATCH 512
#define FEAT  512
#define NID   64
#define GRP   8

// Scratch (device globals; no allocation allowed)
__device__ float g_S[BATCH * BATCH];
__device__ float g_partial[NID];
__device__ __nv_bfloat16 g_fsb[BATCH * FEAT];
__device__ __nv_bfloat16 g_ftb[BATCH * FEAT];

// ---------------------------------------------------------------------------
// Kernel 0: fp32 -> bf16 convert for both inputs.
// 512*512/4 = 65536 float4 elements per tensor; 256 blocks x 256 threads.
// ---------------------------------------------------------------------------
__global__ void __launch_bounds__(256) convert_kernel(const float* __restrict__ fs,
                                                      const float* __restrict__ ft) {
    const int idx = blockIdx.x * 256 + threadIdx.x;   // 0..65535
    const float4 s = ((const float4*)fs)[idx];
    const float4 t = ((const float4*)ft)[idx];
    __nv_bfloat162* so = (__nv_bfloat162*)g_fsb;
    __nv_bfloat162* to = (__nv_bfloat162*)g_ftb;
    so[2 * idx + 0] = __floats2bfloat162_rn(s.x, s.y);
    so[2 * idx + 1] = __floats2bfloat162_rn(s.z, s.w);
    to[2 * idx + 0] = __floats2bfloat162_rn(t.x, t.y);
    to[2 * idx + 1] = __floats2bfloat162_rn(t.z, t.w);
}

// ---------------------------------------------------------------------------
// Kernel 1: S = fs_bf16 @ ft_bf16^T via mma.sync.m16n8k16 (bf16, f32 accum).
// BM=64, BN=32, BK=32. 256 threads = 8 warps as 4(m) x 2(n), warp tile 16x16.
// Grid (16, 8) = 128 blocks. Double-buffered smem + register gmem prefetch.
// ---------------------------------------------------------------------------
__global__ void __launch_bounds__(256) gemm_bf16_kernel() {
    __shared__ __align__(16) __nv_bfloat16 As[2][64][40];  // pad 8 halfs: ldmatrix conflict-free
    __shared__ __align__(16) __nv_bfloat16 Bs[2][32][40];

    const int tid   = threadIdx.x;
    const int mTile = blockIdx.y * 64;
    const int nTile = blockIdx.x * 32;
    const int warp  = tid >> 5;
    const int lane  = tid & 31;
    const int wm    = warp & 3;        // 0..3 -> m offset 16*wm
    const int wn    = warp >> 2;       // 0..1 -> n offset 16*wn

    // gmem loaders: A 64 rows x 4 chunks (16B) -> 256 threads; B 32 rows x 4 -> 128 threads
    const int arow = tid >> 2, achk = (tid & 3) * 8;
    const int brow = (tid & 127) >> 2, bchk = (tid & 3) * 8;
    const bool bld = tid < 128;
    const __nv_bfloat16* agp = g_fsb + (mTile + arow) * FEAT + achk;
    const __nv_bfloat16* bgp = g_ftb + (nTile + brow) * FEAT + bchk;

    uint4 ra = *(const uint4*)agp;
    uint4 rb = bld ? *(const uint4*)bgp : make_uint4(0, 0, 0, 0);

    float acc[2][4] = {};   // two n-halves (8 cols each) of the 16x16 warp tile

    // ldmatrix smem addresses (fixed per lane, k-offset added in loop)
    const int a_row = 16 * wm + (lane & 7) + ((lane >> 3) & 1) * 8;
    const int a_k8  = (lane >> 4) * 8;
    const int b_row = 16 * wn + (lane & 7) + (lane >> 4) * 8;
    const int b_k8  = ((lane >> 3) & 1) * 8;

    #pragma unroll 1
    for (int s = 0; s < 16; s++) {
        const int buf = s & 1;
        *(uint4*)&As[buf][arow][achk] = ra;
        if (bld) *(uint4*)&Bs[buf][brow][bchk] = rb;
        __syncthreads();

        if (s < 15) {
            ra = *(const uint4*)(agp + (s + 1) * 32);
            if (bld) rb = *(const uint4*)(bgp + (s + 1) * 32);
        }

        #pragma unroll
        for (int kk = 0; kk < 2; kk++) {
            const int kb = kk * 16;
            uint32_t a0, a1, a2, a3, b0, b1, b2, b3;
            uint32_t aaddr = (uint32_t)__cvta_generic_to_shared(&As[buf][a_row][kb + a_k8]);
            uint32_t baddr = (uint32_t)__cvta_generic_to_shared(&Bs[buf][b_row][kb + b_k8]);
            asm volatile("ldmatrix.sync.aligned.m8n8.x4.shared.b16 {%0,%1,%2,%3}, [%4];\n"
                         : "=r"(a0), "=r"(a1), "=r"(a2), "=r"(a3) : "r"(aaddr));
            asm volatile("ldmatrix.sync.aligned.m8n8.x4.shared.b16 {%0,%1,%2,%3}, [%4];\n"
                         : "=r"(b0), "=r"(b1), "=r"(b2), "=r"(b3) : "r"(baddr));
            asm volatile("mma.sync.aligned.m16n8k16.row.col.f32.bf16.bf16.f32 "
                         "{%0,%1,%2,%3}, {%4,%5,%6,%7}, {%8,%9}, {%0,%1,%2,%3};\n"
                         : "+f"(acc[0][0]), "+f"(acc[0][1]), "+f"(acc[0][2]), "+f"(acc[0][3])
                         : "r"(a0), "r"(a1), "r"(a2), "r"(a3), "r"(b0), "r"(b1));
            asm volatile("mma.sync.aligned.m16n8k16.row.col.f32.bf16.bf16.f32 "
                         "{%0,%1,%2,%3}, {%4,%5,%6,%7}, {%8,%9}, {%0,%1,%2,%3};\n"
                         : "+f"(acc[1][0]), "+f"(acc[1][1]), "+f"(acc[1][2]), "+f"(acc[1][3])
                         : "r"(a0), "r"(a1), "r"(a2), "r"(a3), "r"(b2), "r"(b3));
        }
        __syncthreads();
    }

    // Epilogue: lane holds d[g][t*2,(t*2)+1] and d[g+8][...] per n-half
    const int g = lane >> 2, t = lane & 3;
    const int row0 = mTile + 16 * wm + g;
    #pragma unroll
    for (int h = 0; h < 2; h++) {
        const int col = nTile + 16 * wn + 8 * h + t * 2;
        *(float2*)&g_S[row0 * BATCH + col]       = make_float2(acc[h][0], acc[h][1]);
        *(float2*)&g_S[(row0 + 8) * BATCH + col] = make_float2(acc[h][2], acc[h][3]);
    }
}

// ---------------------------------------------------------------------------
// Kernel 2: per identity group n (64 blocks, 256 threads)
// ---------------------------------------------------------------------------
__global__ void __launch_bounds__(256) group_kernel() {
    __shared__ float Sr[GRP * BATCH];
    __shared__ float rk_sm[64];
    __shared__ float wsum[2];

    const int n   = blockIdx.x;
    const int tid = threadIdx.x;

    {
        const float4* src = (const float4*)(g_S + n * GRP * BATCH);
        float4* dst = (float4*)Sr;
        #pragma unroll
        for (int v = 0; v < 4; v++) dst[tid + v * 256] = src[tid + v * 256];
    }
    __syncthreads();

    const int p = tid >> 2;
    const int q = tid & 3;
    const int r = p >> 3;
    const int i = p & 7;
    const float sbi = Sr[r * BATCH + n * GRP + i];
    const float* row = Sr + r * BATCH;

    float s = 0.f;
    #pragma unroll 8
    for (int jj = 0; jj < BATCH; jj += 16) {
        float4 v = *(const float4*)(row + jj + q * 4);
        s += fmaxf(v.x - sbi, 0.f) + fmaxf(v.y - sbi, 0.f)
           + fmaxf(v.z - sbi, 0.f) + fmaxf(v.w - sbi, 0.f);
    }
    s += __shfl_down_sync(0xffffffffu, s, 1);
    s += __shfl_down_sync(0xffffffffu, s, 2);
    if (q == 0) rk_sm[p] = 1.f + s;
    __syncthreads();

    float ratio = 0.f;
    if (tid < 64) {
        const int i2 = tid >> 3;
        const int j2 = tid & 7;
        const float* prow = Sr + i2 * BATCH + n * GRP;
        const float pij = prow[j2];
        float ps = 0.f;
        #pragma unroll
        for (int k = 0; k < GRP; k++) ps += fmaxf(prow[k] - pij, 0.f);
        ratio = (1.f + ps) / rk_sm[tid];
    }

    #pragma unroll
    for (int o = 16; o > 0; o >>= 1)
        ratio += __shfl_down_sync(0xffffffffu, ratio, o);
    if (tid < 64 && (tid & 31) == 0) wsum[tid >> 5] = ratio;
    __syncthreads();
    if (tid == 0) g_partial[n] = wsum[0] + wsum[1];
}

// ---------------------------------------------------------------------------
// Kernel 3: final deterministic reduction
// ---------------------------------------------------------------------------
__global__ void final_kernel(float* __restrict__ out) {
    const int tid = threadIdx.x;
    float v = g_partial[tid] + g_partial[tid + 32];
    #pragma unroll
    for (int o = 16; o > 0; o >>= 1)
        v += __shfl_down_sync(0xffffffffu, v, o);
    if (tid == 0) out[0] = 1.f - v * (1.f / 4096.f);
}

extern "C" void kernel_launch(void* const* d_in, const int* in_sizes, int n_in,
                              void* d_out, int out_size) {
    const float* fs = (const float*)d_in[0];
    const float* ft = (const float*)d_in[1];
    float* out = (float*)d_out;

    convert_kernel<<<256, 256>>>(fs, ft);
    gemm_bf16_kernel<<<dim3(16, 8), 256>>>();
    group_kernel<<<NID, 256>>>();
    final_kernel<<<1, 32>>>(out);
}